// round 7
// baseline (speedup 1.0000x reference)
#include <cuda_runtime.h>
#include <cuda_bf16.h>
#include <mma.h>
#include <math.h>
#include <stdint.h>

using namespace nvcuda;

// Problem constants
#define NN      1024
#define DF      6
#define TT      60
#define HH      64
#define GG      192      // 3*H
#define RR      64
#define NEG_VAL (-10000.0f)
#define SLOPE   0.01f

#define WLD     72       // bf16 weight/h leading dim (elements)
#define PLD     200      // f32 preact leading dim

// Inter-kernel scratch
__device__ float g_h1[NN * HH];
__device__ float g_sa[NN];
__device__ float g_sb[NN];
__device__ float g_dot[NN * NN];
__device__ float g_sum[NN * NN];

__device__ __forceinline__ float tanh_fast(float x) {
    float y;
    asm("tanh.approx.f32 %0, %1;" : "=f"(y) : "f"(x));
    return y;
}
__device__ __forceinline__ float sig_fast(float x) {
    return 0.5f * tanh_fast(0.5f * x) + 0.5f;
}
__device__ __forceinline__ void bfsplit(float v, __nv_bfloat16& hi, __nv_bfloat16& lo) {
    hi = __float2bfloat16(v);
    lo = __float2bfloat16(v - __bfloat162float(hi));
}

// ---------------------------------------------------------------------------
// Kernel 1: fused 2-layer GRU, tensor-core (wmma bf16 split-3) version.
// 128 blocks x 8 rows, 384 threads (12 warps = 12 n-tiles of 16 gates).
// ---------------------------------------------------------------------------
#define GT 384
#define GRU_ROWS 8

// smem byte offsets
#define OFF_WHH0HI 0
#define OFF_WHH0LO 27648
#define OFF_WIH1HI 55296
#define OFF_WIH1LO 82944
#define OFF_WHH1HI 110592
#define OFF_WHH1LO 138240
#define OFF_WIH0   165888   // f32 192*8
#define OFF_X      172032   // f32 8*360
#define OFF_XT     183552   // f32 2*64
#define OFF_HAHI   184064   // bf16 16*72
#define OFF_HALO   186368
#define OFF_HBHI   188672
#define OFF_HBLO   190976
#define OFF_P      193280   // f32 16*200
#define OFF_PN     206080   // f32 16*72
#define GRU_SMEM   210688

typedef wmma::fragment<wmma::matrix_a, 16, 16, 16, __nv_bfloat16, wmma::row_major> FragA;
typedef wmma::fragment<wmma::matrix_b, 16, 16, 16, __nv_bfloat16, wmma::col_major> FragB;
typedef wmma::fragment<wmma::accumulator, 16, 16, 16, float> FragC;

__global__ void __launch_bounds__(GT, 1)
gru_kernel(const float* __restrict__ x,
           const float* __restrict__ Wih0, const float* __restrict__ Whh0,
           const float* __restrict__ bih0, const float* __restrict__ bhh0,
           const float* __restrict__ Wih1, const float* __restrict__ Whh1,
           const float* __restrict__ bih1, const float* __restrict__ bhh1,
           const float* __restrict__ Wv)
{
    extern __shared__ char sm[];
    __nv_bfloat16* sWhh0hi = (__nv_bfloat16*)(sm + OFF_WHH0HI);
    __nv_bfloat16* sWhh0lo = (__nv_bfloat16*)(sm + OFF_WHH0LO);
    __nv_bfloat16* sWih1hi = (__nv_bfloat16*)(sm + OFF_WIH1HI);
    __nv_bfloat16* sWih1lo = (__nv_bfloat16*)(sm + OFF_WIH1LO);
    __nv_bfloat16* sWhh1hi = (__nv_bfloat16*)(sm + OFF_WHH1HI);
    __nv_bfloat16* sWhh1lo = (__nv_bfloat16*)(sm + OFF_WHH1LO);
    float* sWih0 = (float*)(sm + OFF_WIH0);
    float* sX    = (float*)(sm + OFF_X);
    float* sXt   = (float*)(sm + OFF_XT);
    __nv_bfloat16* sHAhi = (__nv_bfloat16*)(sm + OFF_HAHI);
    __nv_bfloat16* sHAlo = (__nv_bfloat16*)(sm + OFF_HALO);
    __nv_bfloat16* sHBhi = (__nv_bfloat16*)(sm + OFF_HBHI);
    __nv_bfloat16* sHBlo = (__nv_bfloat16*)(sm + OFF_HBLO);
    float* sP  = (float*)(sm + OFF_P);
    float* sPn = (float*)(sm + OFF_PN);

    const int tid  = threadIdx.x;
    const int warp = tid >> 5;
    const int r0   = blockIdx.x * GRU_ROWS;

    // ---- init: split weights to bf16 hi/lo, load x, zero h buffers ----
    for (int i = tid; i < GG * HH; i += GT) {
        int o = i >> 6, k = i & 63;
        __nv_bfloat16 hi, lo;
        bfsplit(Whh0[i], hi, lo); sWhh0hi[o * WLD + k] = hi; sWhh0lo[o * WLD + k] = lo;
        bfsplit(Wih1[i], hi, lo); sWih1hi[o * WLD + k] = hi; sWih1lo[o * WLD + k] = lo;
        bfsplit(Whh1[i], hi, lo); sWhh1hi[o * WLD + k] = hi; sWhh1lo[o * WLD + k] = lo;
    }
    for (int i = tid; i < GG * DF; i += GT) {
        int o = i / DF, d = i % DF;
        sWih0[o * 8 + d] = Wih0[i];
    }
    for (int i = tid; i < GRU_ROWS * 360; i += GT) {
        int r = i / 360, cc = i % 360;
        sX[i] = x[(size_t)(r0 + r) * 360 + cc];
    }
    for (int i = tid; i < 16 * WLD; i += GT) {
        sHAhi[i] = __float2bfloat16(0.f); sHAlo[i] = __float2bfloat16(0.f);
        sHBhi[i] = __float2bfloat16(0.f); sHBlo[i] = __float2bfloat16(0.f);
    }
    if (tid < GRU_ROWS * DF) {
        int r = tid / DF, d = tid % DF;
        sXt[r * 8 + d] = sX[r * 360 + d * TT + 0];
    }

    // ---- per-item registers (gate-phase ownership) ----
    // item = tid (always), and 384+tid for tid<128
    float h0r[2] = {0.f, 0.f};
    float h1r[2] = {0.f, 0.f};
    float bx0[2][3], bh0[2][3], brz1[2][2], bxn1[2], bhn1[2];
    int   itr[2], itc[2];
    #pragma unroll
    for (int it = 0; it < 2; it++) {
        int item = tid + it * GT;
        if (item < 512) {
            int r = item >> 6, c = item & 63;
            itr[it] = r; itc[it] = c;
            bx0[it][0] = bih0[c]; bx0[it][1] = bih0[64 + c]; bx0[it][2] = bih0[128 + c];
            bh0[it][0] = bhh0[c]; bh0[it][1] = bhh0[64 + c]; bh0[it][2] = bhh0[128 + c];
            brz1[it][0] = bih1[c] + bhh1[c];
            brz1[it][1] = bih1[64 + c] + bhh1[64 + c];
            bxn1[it] = bih1[128 + c];
            bhn1[it] = bhh1[128 + c];
        }
    }
    __syncthreads();

    for (int t = 0; t < TT; ++t) {
        const int cur = t & 1, nxt = cur ^ 1;

        // ===== Phase 1: P = Whh0 * h0_prev  (bf16 split-3) =====
        {
            FragC acc;
            wmma::fill_fragment(acc, 0.f);
            const __nv_bfloat16* bw_hi = sWhh0hi + warp * 16 * WLD;
            const __nv_bfloat16* bw_lo = sWhh0lo + warp * 16 * WLD;
            #pragma unroll
            for (int k = 0; k < 4; k++) {
                FragA ahi, alo; FragB b;
                wmma::load_matrix_sync(ahi, sHAhi + k * 16, WLD);
                wmma::load_matrix_sync(alo, sHAlo + k * 16, WLD);
                wmma::load_matrix_sync(b, bw_hi + k * 16, WLD);
                wmma::mma_sync(acc, ahi, b, acc);
                wmma::mma_sync(acc, alo, b, acc);
                wmma::load_matrix_sync(b, bw_lo + k * 16, WLD);
                wmma::mma_sync(acc, ahi, b, acc);
            }
            wmma::store_matrix_sync(sP + warp * 16, acc, PLD, wmma::mem_row_major);
        }
        __syncthreads();

        // ===== Phase 2: layer-0 gates (x-side scalar), update h0 regs =====
        #pragma unroll
        for (int it = 0; it < 2; it++) {
            int item = tid + it * GT;
            if (item < 512) {
                int r = itr[it], c = itc[it];
                float xr = bx0[it][0], xz = bx0[it][1], xn = bx0[it][2];
                #pragma unroll
                for (int d = 0; d < DF; d++) {
                    float xv = sXt[cur * 64 + r * 8 + d];
                    xr += xv * sWih0[c * 8 + d];
                    xz += xv * sWih0[(64 + c) * 8 + d];
                    xn += xv * sWih0[(128 + c) * 8 + d];
                }
                float hr = sP[r * PLD + c]        + bh0[it][0];
                float hz = sP[r * PLD + 64 + c]   + bh0[it][1];
                float hn = sP[r * PLD + 128 + c]  + bh0[it][2];
                float rv = sig_fast(xr + hr);
                float zv = sig_fast(xz + hz);
                float nv = tanh_fast(xn + rv * hn);
                float hnew = (1.f - zv) * nv + zv * h0r[it];
                h0r[it] = hnew;
                __nv_bfloat16 hi, lo;
                bfsplit(hnew, hi, lo);
                sHAhi[r * WLD + c] = hi;
                sHAlo[r * WLD + c] = lo;
            }
        }
        if (t + 1 < TT && tid < GRU_ROWS * DF) {
            int r = tid / DF, d = tid % DF;
            sXt[nxt * 64 + r * 8 + d] = sX[r * 360 + d * TT + (t + 1)];
        }
        __syncthreads();

        // ===== Phase 3: layer-1 GEMMs =====
        // warps 0-7 (gates 0..127, r/z): acc = Wih1*h0new + Whh1*h1 (combined)
        // warps 8-11 (gates 128..191, n): acc1 = Wih1*h0new, acc2 = Whh1*h1
        if (warp < 8) {
            FragC acc;
            wmma::fill_fragment(acc, 0.f);
            const __nv_bfloat16* u_hi = sWih1hi + warp * 16 * WLD;
            const __nv_bfloat16* u_lo = sWih1lo + warp * 16 * WLD;
            const __nv_bfloat16* w_hi = sWhh1hi + warp * 16 * WLD;
            const __nv_bfloat16* w_lo = sWhh1lo + warp * 16 * WLD;
            #pragma unroll
            for (int k = 0; k < 4; k++) {
                FragA ahi, alo; FragB b;
                wmma::load_matrix_sync(ahi, sHAhi + k * 16, WLD);
                wmma::load_matrix_sync(alo, sHAlo + k * 16, WLD);
                wmma::load_matrix_sync(b, u_hi + k * 16, WLD);
                wmma::mma_sync(acc, ahi, b, acc);
                wmma::mma_sync(acc, alo, b, acc);
                wmma::load_matrix_sync(b, u_lo + k * 16, WLD);
                wmma::mma_sync(acc, ahi, b, acc);
            }
            #pragma unroll
            for (int k = 0; k < 4; k++) {
                FragA ahi, alo; FragB b;
                wmma::load_matrix_sync(ahi, sHBhi + k * 16, WLD);
                wmma::load_matrix_sync(alo, sHBlo + k * 16, WLD);
                wmma::load_matrix_sync(b, w_hi + k * 16, WLD);
                wmma::mma_sync(acc, ahi, b, acc);
                wmma::mma_sync(acc, alo, b, acc);
                wmma::load_matrix_sync(b, w_lo + k * 16, WLD);
                wmma::mma_sync(acc, ahi, b, acc);
            }
            wmma::store_matrix_sync(sP + warp * 16, acc, PLD, wmma::mem_row_major);
        } else {
            FragC acc1, acc2;
            wmma::fill_fragment(acc1, 0.f);
            wmma::fill_fragment(acc2, 0.f);
            const __nv_bfloat16* u_hi = sWih1hi + warp * 16 * WLD;
            const __nv_bfloat16* u_lo = sWih1lo + warp * 16 * WLD;
            const __nv_bfloat16* w_hi = sWhh1hi + warp * 16 * WLD;
            const __nv_bfloat16* w_lo = sWhh1lo + warp * 16 * WLD;
            #pragma unroll
            for (int k = 0; k < 4; k++) {
                FragA ahi, alo; FragB b;
                wmma::load_matrix_sync(ahi, sHAhi + k * 16, WLD);
                wmma::load_matrix_sync(alo, sHAlo + k * 16, WLD);
                wmma::load_matrix_sync(b, u_hi + k * 16, WLD);
                wmma::mma_sync(acc1, ahi, b, acc1);
                wmma::mma_sync(acc1, alo, b, acc1);
                wmma::load_matrix_sync(b, u_lo + k * 16, WLD);
                wmma::mma_sync(acc1, ahi, b, acc1);
            }
            #pragma unroll
            for (int k = 0; k < 4; k++) {
                FragA ahi, alo; FragB b;
                wmma::load_matrix_sync(ahi, sHBhi + k * 16, WLD);
                wmma::load_matrix_sync(alo, sHBlo + k * 16, WLD);
                wmma::load_matrix_sync(b, w_hi + k * 16, WLD);
                wmma::mma_sync(acc2, ahi, b, acc2);
                wmma::mma_sync(acc2, alo, b, acc2);
                wmma::load_matrix_sync(b, w_lo + k * 16, WLD);
                wmma::mma_sync(acc2, ahi, b, acc2);
            }
            wmma::store_matrix_sync(sP + warp * 16, acc1, PLD, wmma::mem_row_major);
            wmma::store_matrix_sync(sPn + (warp - 8) * 16, acc2, WLD, wmma::mem_row_major);
        }
        __syncthreads();

        // ===== Phase 4: layer-1 gates, update h1 regs =====
        #pragma unroll
        for (int it = 0; it < 2; it++) {
            int item = tid + it * GT;
            if (item < 512) {
                int r = itr[it], c = itc[it];
                float sr = sP[r * PLD + c]       + brz1[it][0];
                float sz = sP[r * PLD + 64 + c]  + brz1[it][1];
                float xn = sP[r * PLD + 128 + c] + bxn1[it];
                float hn = sPn[r * WLD + c]      + bhn1[it];
                float rv = sig_fast(sr);
                float zv = sig_fast(sz);
                float nv = tanh_fast(xn + rv * hn);
                float hnew = (1.f - zv) * nv + zv * h1r[it];
                h1r[it] = hnew;
                __nv_bfloat16 hi, lo;
                bfsplit(hnew, hi, lo);
                sHBhi[r * WLD + c] = hi;
                sHBlo[r * WLD + c] = lo;
            }
        }
        __syncthreads();
    }

    // ---- epilogue: final h1 f32 to smem, then globals ----
    float* hf = sP;   // reuse as [8][64]
    #pragma unroll
    for (int it = 0; it < 2; it++) {
        int item = tid + it * GT;
        if (item < 512) hf[item] = h1r[it];
    }
    __syncthreads();

    for (int i = tid; i < GRU_ROWS * HH; i += GT)
        g_h1[(size_t)r0 * HH + i] = hf[i];
    if (tid < GRU_ROWS) {
        float a = 0.f, b2s = 0.f;
        #pragma unroll
        for (int cc = 0; cc < HH; cc++) {
            float h = hf[tid * HH + cc];
            a   += h * Wv[cc];
            b2s += h * Wv[HH + cc];
        }
        g_sa[r0 + tid] = a;
        g_sb[r0 + tid] = b2s;
    }
}

// ---------------------------------------------------------------------------
// Kernel 2: streaming rel-dot (unchanged).
// ---------------------------------------------------------------------------
#define RD_THREADS 256
#define RD_BLOCKS  2048

__global__ void __launch_bounds__(RD_THREADS)
reldot_kernel(const float* __restrict__ rel, const float* __restrict__ W)
{
    __shared__ float sWv[RR];
    const int tid = threadIdx.x;
    if (tid < RR) sWv[tid] = W[2 * HH + tid];
    __syncthreads();

    const int lane16 = tid & 15;
    const int grp    = tid >> 4;
    const float4 wv  = *(const float4*)&sWv[lane16 * 4];
    const int stride = RD_BLOCKS * 16;

    for (int p = blockIdx.x * 16 + grp; p < NN * NN; p += stride) {
        float4 v = *(const float4*)&rel[(size_t)p * RR + lane16 * 4];
        float dot  = v.x * wv.x + v.y * wv.y + v.z * wv.z + v.w * wv.w;
        float ssum = v.x + v.y + v.z + v.w;
        #pragma unroll
        for (int off = 8; off; off >>= 1) {
            dot  += __shfl_xor_sync(0xffffffffu, dot,  off);
            ssum += __shfl_xor_sync(0xffffffffu, ssum, off);
        }
        if (lane16 == 0) {
            g_dot[p] = dot;
            g_sum[p] = ssum;
        }
    }
}

// ---------------------------------------------------------------------------
// Kernel 3: softmax + agg + FC, 8 rows per block (unchanged).
// ---------------------------------------------------------------------------
#define A3_THREADS 512

__global__ void __launch_bounds__(A3_THREADS)
att3_kernel(const float* __restrict__ bsc,
            const float* __restrict__ fc_w,
            const float* __restrict__ fc_b,
            float* __restrict__ out)
{
    __shared__ float sP[8 * NN];
    __shared__ float sT[64 * 64];
    __shared__ float sWmax[16];
    __shared__ float sWsum[16];
    __shared__ float sDen[8];
    __shared__ float sRed[16];

    const int tid  = threadIdx.x;
    const int wid  = tid >> 5;
    const int lane = tid & 31;
    const int i0   = blockIdx.x * 8;

    const int r    = wid >> 1;
    const int part = ((wid & 1) << 5) + lane;
    const int i    = i0 + r;
    const float sa_i = g_sa[i];
    const float bval = bsc[0];

    float tv[16];
    float mx = -INFINITY;
    #pragma unroll
    for (int q4 = 0; q4 < 4; q4++) {
        int j = part * 16 + q4 * 4;
        float4 d4 = *(const float4*)&g_dot[(size_t)i * NN + j];
        float4 s4 = *(const float4*)&g_sum[(size_t)i * NN + j];
        #pragma unroll
        for (int e = 0; e < 4; e++) {
            float dot  = (&d4.x)[e];
            float ssum = (&s4.x)[e];
            float w = sa_i + g_sb[j + e] + dot + bval;
            w = (w >= 0.f) ? w : SLOPE * w;
            float m  = (ssum != 0.f) ? 1.f : 0.f;
            float t  = m * w;
            if (t == 0.f) t = NEG_VAL;
            tv[q4 * 4 + e] = t;
            sP[r * NN + j + e] = m;
            mx = fmaxf(mx, t);
        }
    }
    #pragma unroll
    for (int off = 16; off; off >>= 1) mx = fmaxf(mx, __shfl_xor_sync(0xffffffffu, mx, off));
    if (lane == 0) sWmax[wid] = mx;
    __syncthreads();
    mx = fmaxf(sWmax[r * 2], sWmax[r * 2 + 1]);

    float lsum = 0.f;
    #pragma unroll
    for (int q = 0; q < 16; q++) {
        int j = part * 16 + q;
        float e = __expf(tv[q] - mx);
        lsum += e;
        sP[r * NN + j] = e * sP[r * NN + j];
    }
    #pragma unroll
    for (int off = 16; off; off >>= 1) lsum += __shfl_xor_sync(0xffffffffu, lsum, off);
    if (lane == 0) sWsum[wid] = lsum;
    __syncthreads();
    if (tid < 8) sDen[tid] = sWsum[tid * 2] + sWsum[tid * 2 + 1];
    __syncthreads();

    const int c  = tid & 63;
    const int rr = tid >> 6;
    float acc = 0.f;
    for (int tile = 0; tile < 16; tile++) {
        #pragma unroll
        for (int k = 0; k < 8; k++) {
            int e = tid + k * A3_THREADS;
            sT[e] = g_h1[(size_t)(tile * 64) * HH + e];
        }
        __syncthreads();
        const float* pr = &sP[rr * NN + tile * 64];
        #pragma unroll 16
        for (int jj = 0; jj < 64; jj++)
            acc += pr[jj] * sT[jj * 64 + c];
        __syncthreads();
    }

    const float inv = 1.0f / sDen[rr];
    float val = g_h1[(size_t)(i0 + rr) * HH + c] * fc_w[c] + acc * inv * fc_w[HH + c];
    #pragma unroll
    for (int off = 16; off; off >>= 1) val += __shfl_xor_sync(0xffffffffu, val, off);
    if (lane == 0) sRed[wid] = val;
    __syncthreads();
    if (tid < 8)
        out[i0 + tid] = sRed[tid * 2] + sRed[tid * 2 + 1] + fc_b[0];
}

// ---------------------------------------------------------------------------
// Launch: fork reldot onto a side stream to overlap the GRU.
// ---------------------------------------------------------------------------
extern "C" void kernel_launch(void* const* d_in, const int* in_sizes, int n_in,
                              void* d_out, int out_size)
{
    const float* x    = (const float*)d_in[0];
    const float* rel  = (const float*)d_in[1];
    const float* W    = (const float*)d_in[2];
    const float* b    = (const float*)d_in[3];
    const float* fc_w = (const float*)d_in[4];
    const float* fc_b = (const float*)d_in[5];
    const float* Wih0 = (const float*)d_in[6];
    const float* Whh0 = (const float*)d_in[7];
    const float* bih0 = (const float*)d_in[8];
    const float* bhh0 = (const float*)d_in[9];
    const float* Wih1 = (const float*)d_in[10];
    const float* Whh1 = (const float*)d_in[11];
    const float* bih1 = (const float*)d_in[12];
    const float* bhh1 = (const float*)d_in[13];
    float* out = (float*)d_out;

    cudaFuncSetAttribute(gru_kernel, cudaFuncAttributeMaxDynamicSharedMemorySize,
                         GRU_SMEM);

    cudaStream_t s1;
    cudaEvent_t eFork, eJoin;
    cudaStreamCreateWithFlags(&s1, cudaStreamNonBlocking);
    cudaEventCreateWithFlags(&eFork, cudaEventDisableTiming);
    cudaEventCreateWithFlags(&eJoin, cudaEventDisableTiming);

    cudaEventRecord(eFork, 0);
    cudaStreamWaitEvent(s1, eFork, 0);

    reldot_kernel<<<RD_BLOCKS, RD_THREADS, 0, s1>>>(rel, W);
    cudaEventRecord(eJoin, s1);

    gru_kernel<<<NN / GRU_ROWS, GT, GRU_SMEM>>>(
        x, Wih0, Whh0, bih0, bhh0, Wih1, Whh1, bih1, bhh1, W);

    cudaStreamWaitEvent(0, eJoin, 0);

    att3_kernel<<<NN / 8, A3_THREADS>>>(b, fc_w, fc_b, out);
}

// round 8
// speedup vs baseline: 1.2039x; 1.2039x over previous
#include <cuda_runtime.h>
#include <math.h>
#include <stdint.h>

// Problem constants
#define NN      1024
#define DF      6
#define TT      60
#define HH      64
#define GG      192      // 3*H
#define RR      64
#define WPAD    68
#define HPAD    68
#define NEG_VAL (-10000.0f)
#define SLOPE   0.01f

// Inter-kernel scratch
__device__ float g_h1[NN * HH];
__device__ float g_sa[NN];
__device__ float g_sb[NN];
__device__ float g_dot[NN * NN];
__device__ float g_sum[NN * NN];

typedef unsigned long long u64;

__device__ __forceinline__ u64 ffma2(u64 a, u64 b, u64 c) {
    u64 d;
    asm("fma.rn.f32x2 %0, %1, %2, %3;" : "=l"(d) : "l"(a), "l"(b), "l"(c));
    return d;
}
__device__ __forceinline__ float hsum2(u64 v) {
    float lo, hi;
    asm("mov.b64 {%0,%1}, %2;" : "=f"(lo), "=f"(hi) : "l"(v));
    return lo + hi;
}
__device__ __forceinline__ float tanh_fast(float x) {
    float y;
    asm("tanh.approx.f32 %0, %1;" : "=f"(y) : "f"(x));
    return y;
}
__device__ __forceinline__ float sig_fast(float x) {
    return 0.5f * tanh_fast(0.5f * x) + 0.5f;
}

// Compacting 4-lane reduction over kq (lane bits 0-1). After this, the caller
// lane owns row rfin = (kq&1)*2 + (kq>>1) with the fully-reduced value.
#define REDUCE4(v0, v1, v2, v3, out)                                          \
    {                                                                         \
        float _t0 = __shfl_xor_sync(0xffffffffu, hiA ? (v0) : (v2), 1);       \
        float _t1 = __shfl_xor_sync(0xffffffffu, hiA ? (v1) : (v3), 1);       \
        float _va = (hiA ? (v2) : (v0)) + _t0;                                \
        float _vb = (hiA ? (v3) : (v1)) + _t1;                                \
        float _t2 = __shfl_xor_sync(0xffffffffu, hiB ? _va : _vb, 2);         \
        (out) = (hiB ? _vb : _va) + _t2;                                      \
    }

// ---------------------------------------------------------------------------
// Kernel 1: fused 2-layer GRU v3 (r=4 rows/group, gc=2 cols, s=4 K-split).
// 128 blocks x 8 rows, 256 threads.
// ---------------------------------------------------------------------------
#define GRU_THREADS 256
#define GRU_ROWS    8

__global__ void __launch_bounds__(GRU_THREADS, 1)
gru_kernel(const float* __restrict__ x,
           const float* __restrict__ Wih0, const float* __restrict__ Whh0,
           const float* __restrict__ bih0, const float* __restrict__ bhh0,
           const float* __restrict__ Wih1, const float* __restrict__ Whh1,
           const float* __restrict__ bih1, const float* __restrict__ bhh1,
           const float* __restrict__ Wv)
{
    extern __shared__ float smem[];
    float* sWhh0 = smem;                          // 192*68
    float* sWih1 = sWhh0 + GG * WPAD;             // 192*68
    float* sWhh1 = sWih1 + GG * WPAD;             // 192*68
    float* sWih0 = sWhh1 + GG * WPAD;             // 192*8
    float* sX    = sWih0 + GG * 8;                // 8*360
    float* sXt   = sX + GRU_ROWS * 360;           // 2*64
    float* sH0   = sXt + 2 * 64;                  // 2*8*68 (double buffer)
    float* sH1   = sH0 + 2 * GRU_ROWS * HPAD;     // 2*8*68

    const int tid = threadIdx.x;
    const int r0  = blockIdx.x * GRU_ROWS;

    for (int i = tid; i < GG * HH; i += GRU_THREADS) {
        int o = i >> 6, k = i & 63;
        sWhh0[o * WPAD + k] = Whh0[i];
        sWih1[o * WPAD + k] = Wih1[i];
        sWhh1[o * WPAD + k] = Whh1[i];
    }
    for (int i = tid; i < GG * DF; i += GRU_THREADS) {
        int o = i / DF, d = i % DF;
        sWih0[o * 8 + d] = Wih0[i];
    }
    for (int i = tid; i < GRU_ROWS * 360; i += GRU_THREADS) {
        int r = i / 360, cc = i % 360;
        sX[i] = x[(size_t)(r0 + r) * 360 + cc];
    }
    for (int i = tid; i < 2 * GRU_ROWS * HPAD; i += GRU_THREADS) {
        sH0[i] = 0.f; sH1[i] = 0.f;
    }
    if (tid < GRU_ROWS * DF) {
        int r = tid / DF, d = tid % DF;
        sXt[r * 8 + d] = sX[r * 360 + d * TT + 0];
    }

    // thread mapping
    const int lane  = tid & 31;
    const int warp  = tid >> 5;
    const int kq    = lane & 3;            // K split index (stride-4 chunks)
    const int rg    = (lane >> 2) & 1;     // row group
    const int cpl   = lane >> 3;           // 0..3
    const int cp    = warp * 4 + cpl;      // 0..31
    const int rbase = rg * 4;
    const int c0    = cp;
    const int c1    = cp + 32;
    const bool hiA  = (kq & 1);
    const bool hiB  = ((kq >> 1) & 1);
    const int rfin  = (kq & 1) * 2 + (kq >> 1);
    const int myrow = rbase + rfin;

    // per-lane biases for cols {c0, c1}
    float br0[2], bz0[2], bxn0[2], bhn0[2];
    float br1[2], bz1[2], bxn1[2], bhn1[2];
    {
        const int cc[2] = {c0, c1};
        #pragma unroll
        for (int j = 0; j < 2; j++) {
            br0[j]  = bih0[cc[j]] + bhh0[cc[j]];
            bz0[j]  = bih0[64 + cc[j]] + bhh0[64 + cc[j]];
            bxn0[j] = bih0[128 + cc[j]];
            bhn0[j] = bhh0[128 + cc[j]];
            br1[j]  = bih1[cc[j]] + bhh1[cc[j]];
            bz1[j]  = bih1[64 + cc[j]] + bhh1[64 + cc[j]];
            bxn1[j] = bih1[128 + cc[j]];
            bhn1[j] = bhh1[128 + cc[j]];
        }
    }
    __syncthreads();

    for (int t = 0; t < TT; ++t) {
        const int cur = t & 1, nxt = cur ^ 1;
        float* sH0c = sH0 + cur * (GRU_ROWS * HPAD);
        float* sH0n = sH0 + nxt * (GRU_ROWS * HPAD);
        float* sH1c = sH1 + cur * (GRU_ROWS * HPAD);
        float* sH1n = sH1 + nxt * (GRU_ROWS * HPAD);

        // ================= layer 0: gemm + reduce + gates =================
        {
            u64 Ar[4][2], Az[4][2], An[4][2];
            #pragma unroll
            for (int i = 0; i < 4; i++)
                #pragma unroll
                for (int j = 0; j < 2; j++) { Ar[i][j] = 0; Az[i][j] = 0; An[i][j] = 0; }

            #pragma unroll
            for (int q = 0; q < 4; q++) {
                const int k4 = q * 4 + kq;
                ulonglong2 wr0 = *(const ulonglong2*)&sWhh0[c0 * WPAD + k4 * 4];
                ulonglong2 wr1 = *(const ulonglong2*)&sWhh0[c1 * WPAD + k4 * 4];
                ulonglong2 wz0 = *(const ulonglong2*)&sWhh0[(64 + c0) * WPAD + k4 * 4];
                ulonglong2 wz1 = *(const ulonglong2*)&sWhh0[(64 + c1) * WPAD + k4 * 4];
                ulonglong2 wn0 = *(const ulonglong2*)&sWhh0[(128 + c0) * WPAD + k4 * 4];
                ulonglong2 wn1 = *(const ulonglong2*)&sWhh0[(128 + c1) * WPAD + k4 * 4];
                #pragma unroll
                for (int i = 0; i < 4; i++) {
                    ulonglong2 hv = *(const ulonglong2*)&sH0c[(rbase + i) * HPAD + k4 * 4];
                    Ar[i][0] = ffma2(hv.x, wr0.x, Ar[i][0]);
                    Ar[i][1] = ffma2(hv.x, wr1.x, Ar[i][1]);
                    Az[i][0] = ffma2(hv.x, wz0.x, Az[i][0]);
                    Az[i][1] = ffma2(hv.x, wz1.x, Az[i][1]);
                    An[i][0] = ffma2(hv.x, wn0.x, An[i][0]);
                    An[i][1] = ffma2(hv.x, wn1.x, An[i][1]);
                    Ar[i][0] = ffma2(hv.y, wr0.y, Ar[i][0]);
                    Ar[i][1] = ffma2(hv.y, wr1.y, Ar[i][1]);
                    Az[i][0] = ffma2(hv.y, wz0.y, Az[i][0]);
                    Az[i][1] = ffma2(hv.y, wz1.y, Az[i][1]);
                    An[i][0] = ffma2(hv.y, wn0.y, An[i][0]);
                    An[i][1] = ffma2(hv.y, wn1.y, An[i][1]);
                }
            }

            float hr[2], hz[2], hn[2];
            #pragma unroll
            for (int j = 0; j < 2; j++) {
                float v0, v1, v2, v3;
                v0 = hsum2(Ar[0][j]); v1 = hsum2(Ar[1][j]);
                v2 = hsum2(Ar[2][j]); v3 = hsum2(Ar[3][j]);
                REDUCE4(v0, v1, v2, v3, hr[j]);
                v0 = hsum2(Az[0][j]); v1 = hsum2(Az[1][j]);
                v2 = hsum2(Az[2][j]); v3 = hsum2(Az[3][j]);
                REDUCE4(v0, v1, v2, v3, hz[j]);
                v0 = hsum2(An[0][j]); v1 = hsum2(An[1][j]);
                v2 = hsum2(An[2][j]); v3 = hsum2(An[3][j]);
                REDUCE4(v0, v1, v2, v3, hn[j]);
            }

            // x-side + gates, owner lane: row = myrow, cols c0/c1
            const int cc[2] = {c0, c1};
            #pragma unroll
            for (int j = 0; j < 2; j++) {
                float xr = 0.f, xz = 0.f, xn = 0.f;
                #pragma unroll
                for (int d = 0; d < DF; d++) {
                    float xv = sXt[cur * 64 + myrow * 8 + d];
                    xr += xv * sWih0[cc[j] * 8 + d];
                    xz += xv * sWih0[(64 + cc[j]) * 8 + d];
                    xn += xv * sWih0[(128 + cc[j]) * 8 + d];
                }
                float rv = sig_fast(xr + hr[j] + br0[j]);
                float zv = sig_fast(xz + hz[j] + bz0[j]);
                float nv = tanh_fast(xn + bxn0[j] + rv * (hn[j] + bhn0[j]));
                float ho = sH0c[myrow * HPAD + cc[j]];
                sH0n[myrow * HPAD + cc[j]] = (1.f - zv) * nv + zv * ho;
            }
        }
        if (t + 1 < TT && tid < GRU_ROWS * DF) {
            int r = tid / DF, d = tid % DF;
            sXt[nxt * 64 + r * 8 + d] = sX[r * 360 + d * TT + (t + 1)];
        }
        __syncthreads();

        // ================= layer 1: gemm + reduce + gates =================
        {
            u64 Cr[4][2], Cz[4][2], Cxn[4][2], Chn[4][2];
            #pragma unroll
            for (int i = 0; i < 4; i++)
                #pragma unroll
                for (int j = 0; j < 2; j++) { Cr[i][j] = 0; Cz[i][j] = 0; Cxn[i][j] = 0; Chn[i][j] = 0; }

            #pragma unroll
            for (int q = 0; q < 4; q++) {
                const int k4 = q * 4 + kq;
                ulonglong2 ur0 = *(const ulonglong2*)&sWih1[c0 * WPAD + k4 * 4];
                ulonglong2 ur1 = *(const ulonglong2*)&sWih1[c1 * WPAD + k4 * 4];
                ulonglong2 uz0 = *(const ulonglong2*)&sWih1[(64 + c0) * WPAD + k4 * 4];
                ulonglong2 uz1 = *(const ulonglong2*)&sWih1[(64 + c1) * WPAD + k4 * 4];
                ulonglong2 un0 = *(const ulonglong2*)&sWih1[(128 + c0) * WPAD + k4 * 4];
                ulonglong2 un1 = *(const ulonglong2*)&sWih1[(128 + c1) * WPAD + k4 * 4];
                ulonglong2 wr0 = *(const ulonglong2*)&sWhh1[c0 * WPAD + k4 * 4];
                ulonglong2 wr1 = *(const ulonglong2*)&sWhh1[c1 * WPAD + k4 * 4];
                ulonglong2 wz0 = *(const ulonglong2*)&sWhh1[(64 + c0) * WPAD + k4 * 4];
                ulonglong2 wz1 = *(const ulonglong2*)&sWhh1[(64 + c1) * WPAD + k4 * 4];
                ulonglong2 wn0 = *(const ulonglong2*)&sWhh1[(128 + c0) * WPAD + k4 * 4];
                ulonglong2 wn1 = *(const ulonglong2*)&sWhh1[(128 + c1) * WPAD + k4 * 4];
                #pragma unroll
                for (int i = 0; i < 4; i++) {
                    ulonglong2 gv = *(const ulonglong2*)&sH0n[(rbase + i) * HPAD + k4 * 4];
                    ulonglong2 vv = *(const ulonglong2*)&sH1c[(rbase + i) * HPAD + k4 * 4];
                    Cr[i][0]  = ffma2(gv.x, ur0.x, Cr[i][0]);
                    Cr[i][0]  = ffma2(vv.x, wr0.x, Cr[i][0]);
                    Cr[i][1]  = ffma2(gv.x, ur1.x, Cr[i][1]);
                    Cr[i][1]  = ffma2(vv.x, wr1.x, Cr[i][1]);
                    Cz[i][0]  = ffma2(gv.x, uz0.x, Cz[i][0]);
                    Cz[i][0]  = ffma2(vv.x, wz0.x, Cz[i][0]);
                    Cz[i][1]  = ffma2(gv.x, uz1.x, Cz[i][1]);
                    Cz[i][1]  = ffma2(vv.x, wz1.x, Cz[i][1]);
                    Cxn[i][0] = ffma2(gv.x, un0.x, Cxn[i][0]);
                    Cxn[i][1] = ffma2(gv.x, un1.x, Cxn[i][1]);
                    Chn[i][0] = ffma2(vv.x, wn0.x, Chn[i][0]);
                    Chn[i][1] = ffma2(vv.x, wn1.x, Chn[i][1]);
                    Cr[i][0]  = ffma2(gv.y, ur0.y, Cr[i][0]);
                    Cr[i][0]  = ffma2(vv.y, wr0.y, Cr[i][0]);
                    Cr[i][1]  = ffma2(gv.y, ur1.y, Cr[i][1]);
                    Cr[i][1]  = ffma2(vv.y, wr1.y, Cr[i][1]);
                    Cz[i][0]  = ffma2(gv.y, uz0.y, Cz[i][0]);
                    Cz[i][0]  = ffma2(vv.y, wz0.y, Cz[i][0]);
                    Cz[i][1]  = ffma2(gv.y, uz1.y, Cz[i][1]);
                    Cz[i][1]  = ffma2(vv.y, wz1.y, Cz[i][1]);
                    Cxn[i][0] = ffma2(gv.y, un0.y, Cxn[i][0]);
                    Cxn[i][1] = ffma2(gv.y, un1.y, Cxn[i][1]);
                    Chn[i][0] = ffma2(vv.y, wn0.y, Chn[i][0]);
                    Chn[i][1] = ffma2(vv.y, wn1.y, Chn[i][1]);
                }
            }

            const int cc[2] = {c0, c1};
            #pragma unroll
            for (int j = 0; j < 2; j++) {
                float sr, sz, xn, hn;
                float v0, v1, v2, v3;
                v0 = hsum2(Cr[0][j]); v1 = hsum2(Cr[1][j]);
                v2 = hsum2(Cr[2][j]); v3 = hsum2(Cr[3][j]);
                REDUCE4(v0, v1, v2, v3, sr);
                v0 = hsum2(Cz[0][j]); v1 = hsum2(Cz[1][j]);
                v2 = hsum2(Cz[2][j]); v3 = hsum2(Cz[3][j]);
                REDUCE4(v0, v1, v2, v3, sz);
                v0 = hsum2(Cxn[0][j]); v1 = hsum2(Cxn[1][j]);
                v2 = hsum2(Cxn[2][j]); v3 = hsum2(Cxn[3][j]);
                REDUCE4(v0, v1, v2, v3, xn);
                v0 = hsum2(Chn[0][j]); v1 = hsum2(Chn[1][j]);
                v2 = hsum2(Chn[2][j]); v3 = hsum2(Chn[3][j]);
                REDUCE4(v0, v1, v2, v3, hn);

                float rv = sig_fast(sr + br1[j]);
                float zv = sig_fast(sz + bz1[j]);
                float nv = tanh_fast(xn + bxn1[j] + rv * (hn + bhn1[j]));
                float ho = sH1c[myrow * HPAD + cc[j]];
                sH1n[myrow * HPAD + cc[j]] = (1.f - zv) * nv + zv * ho;
            }
        }
        __syncthreads();
    }

    // final h1 buffer = TT & 1
    const float* hf = sH1 + (TT & 1) * (GRU_ROWS * HPAD);
    for (int i = tid; i < GRU_ROWS * HH; i += GRU_THREADS) {
        int r = i >> 6, c = i & 63;
        g_h1[(size_t)r0 * HH + i] = hf[r * HPAD + c];
    }
    if (tid < GRU_ROWS) {
        float a = 0.f, b2s = 0.f;
        #pragma unroll
        for (int cc2 = 0; cc2 < HH; cc2++) {
            float h = hf[tid * HPAD + cc2];
            a   += h * Wv[cc2];
            b2s += h * Wv[HH + cc2];
        }
        g_sa[r0 + tid] = a;
        g_sb[r0 + tid] = b2s;
    }
}

// ---------------------------------------------------------------------------
// Kernel 2: streaming rel-dot (unchanged).
// ---------------------------------------------------------------------------
#define RD_THREADS 256
#define RD_BLOCKS  2048

__global__ void __launch_bounds__(RD_THREADS)
reldot_kernel(const float* __restrict__ rel, const float* __restrict__ W)
{
    __shared__ float sWv[RR];
    const int tid = threadIdx.x;
    if (tid < RR) sWv[tid] = W[2 * HH + tid];
    __syncthreads();

    const int lane16 = tid & 15;
    const int grp    = tid >> 4;
    const float4 wv  = *(const float4*)&sWv[lane16 * 4];
    const int stride = RD_BLOCKS * 16;

    for (int p = blockIdx.x * 16 + grp; p < NN * NN; p += stride) {
        float4 v = *(const float4*)&rel[(size_t)p * RR + lane16 * 4];
        float dot  = v.x * wv.x + v.y * wv.y + v.z * wv.z + v.w * wv.w;
        float ssum = v.x + v.y + v.z + v.w;
        #pragma unroll
        for (int off = 8; off; off >>= 1) {
            dot  += __shfl_xor_sync(0xffffffffu, dot,  off);
            ssum += __shfl_xor_sync(0xffffffffu, ssum, off);
        }
        if (lane16 == 0) {
            g_dot[p] = dot;
            g_sum[p] = ssum;
        }
    }
}

// ---------------------------------------------------------------------------
// Kernel 3: softmax + agg + FC, 8 rows per block (unchanged).
// ---------------------------------------------------------------------------
#define A3_THREADS 512

__global__ void __launch_bounds__(A3_THREADS)
att3_kernel(const float* __restrict__ bsc,
            const float* __restrict__ fc_w,
            const float* __restrict__ fc_b,
            float* __restrict__ out)
{
    __shared__ float sP[8 * NN];
    __shared__ float sT[64 * 64];
    __shared__ float sWmax[16];
    __shared__ float sWsum[16];
    __shared__ float sDen[8];
    __shared__ float sRed[16];

    const int tid  = threadIdx.x;
    const int wid  = tid >> 5;
    const int lane = tid & 31;
    const int i0   = blockIdx.x * 8;

    const int r    = wid >> 1;
    const int part = ((wid & 1) << 5) + lane;
    const int i    = i0 + r;
    const float sa_i = g_sa[i];
    const float bval = bsc[0];

    float tv[16];
    float mx = -INFINITY;
    #pragma unroll
    for (int q4 = 0; q4 < 4; q4++) {
        int j = part * 16 + q4 * 4;
        float4 d4 = *(const float4*)&g_dot[(size_t)i * NN + j];
        float4 s4 = *(const float4*)&g_sum[(size_t)i * NN + j];
        #pragma unroll
        for (int e = 0; e < 4; e++) {
            float dot  = (&d4.x)[e];
            float ssum = (&s4.x)[e];
            float w = sa_i + g_sb[j + e] + dot + bval;
            w = (w >= 0.f) ? w : SLOPE * w;
            float m  = (ssum != 0.f) ? 1.f : 0.f;
            float t  = m * w;
            if (t == 0.f) t = NEG_VAL;
            tv[q4 * 4 + e] = t;
            sP[r * NN + j + e] = m;
            mx = fmaxf(mx, t);
        }
    }
    #pragma unroll
    for (int off = 16; off; off >>= 1) mx = fmaxf(mx, __shfl_xor_sync(0xffffffffu, mx, off));
    if (lane == 0) sWmax[wid] = mx;
    __syncthreads();
    mx = fmaxf(sWmax[r * 2], sWmax[r * 2 + 1]);

    float lsum = 0.f;
    #pragma unroll
    for (int q = 0; q < 16; q++) {
        int j = part * 16 + q;
        float e = __expf(tv[q] - mx);
        lsum += e;
        sP[r * NN + j] = e * sP[r * NN + j];
    }
    #pragma unroll
    for (int off = 16; off; off >>= 1) lsum += __shfl_xor_sync(0xffffffffu, lsum, off);
    if (lane == 0) sWsum[wid] = lsum;
    __syncthreads();
    if (tid < 8) sDen[tid] = sWsum[tid * 2] + sWsum[tid * 2 + 1];
    __syncthreads();

    const int c  = tid & 63;
    const int rr = tid >> 6;
    float acc = 0.f;
    for (int tile = 0; tile < 16; tile++) {
        #pragma unroll
        for (int k = 0; k < 8; k++) {
            int e = tid + k * A3_THREADS;
            sT[e] = g_h1[(size_t)(tile * 64) * HH + e];
        }
        __syncthreads();
        const float* pr = &sP[rr * NN + tile * 64];
        #pragma unroll 16
        for (int jj = 0; jj < 64; jj++)
            acc += pr[jj] * sT[jj * 64 + c];
        __syncthreads();
    }

    const float inv = 1.0f / sDen[rr];
    float val = g_h1[(size_t)(i0 + rr) * HH + c] * fc_w[c] + acc * inv * fc_w[HH + c];
    #pragma unroll
    for (int off = 16; off; off >>= 1) val += __shfl_xor_sync(0xffffffffu, val, off);
    if (lane == 0) sRed[wid] = val;
    __syncthreads();
    if (tid < 8)
        out[i0 + tid] = sRed[tid * 2] + sRed[tid * 2 + 1] + fc_b[0];
}

// ---------------------------------------------------------------------------
// Launch: gru on main stream first, reldot forked alongside it.
// ---------------------------------------------------------------------------
extern "C" void kernel_launch(void* const* d_in, const int* in_sizes, int n_in,
                              void* d_out, int out_size)
{
    const float* x    = (const float*)d_in[0];
    const float* rel  = (const float*)d_in[1];
    const float* W    = (const float*)d_in[2];
    const float* b    = (const float*)d_in[3];
    const float* fc_w = (const float*)d_in[4];
    const float* fc_b = (const float*)d_in[5];
    const float* Wih0 = (const float*)d_in[6];
    const float* Whh0 = (const float*)d_in[7];
    const float* bih0 = (const float*)d_in[8];
    const float* bhh0 = (const float*)d_in[9];
    const float* Wih1 = (const float*)d_in[10];
    const float* Whh1 = (const float*)d_in[11];
    const float* bih1 = (const float*)d_in[12];
    const float* bhh1 = (const float*)d_in[13];
    float* out = (float*)d_out;

    const size_t gru_smem =
        (3 * GG * WPAD + GG * 8 + GRU_ROWS * 360 + 2 * 64 +
         4 * GRU_ROWS * HPAD) * sizeof(float);
    cudaFuncSetAttribute(gru_kernel, cudaFuncAttributeMaxDynamicSharedMemorySize,
                         (int)gru_smem);

    cudaStream_t s1;
    cudaEvent_t eFork, eJoin;
    cudaStreamCreateWithFlags(&s1, cudaStreamNonBlocking);
    cudaEventCreateWithFlags(&eFork, cudaEventDisableTiming);
    cudaEventCreateWithFlags(&eJoin, cudaEventDisableTiming);

    cudaEventRecord(eFork, 0);
    cudaStreamWaitEvent(s1, eFork, 0);

    gru_kernel<<<NN / GRU_ROWS, GRU_THREADS, gru_smem>>>(
        x, Wih0, Whh0, bih0, bhh0, Wih1, Whh1, bih1, bhh1, W);

    reldot_kernel<<<RD_BLOCKS, RD_THREADS, 0, s1>>>(rel, W);
    cudaEventRecord(eJoin, s1);

    cudaStreamWaitEvent(0, eJoin, 0);

    att3_kernel<<<NN / 8, A3_THREADS>>>(b, fc_w, fc_b, out);
}